// round 10
// baseline (speedup 1.0000x reference)
#include <cuda_runtime.h>
#include <cuda_bf16.h>
#include <cstdint>

#define N_NODES 50000
#define N_EDGES 800000
#define IN_DIM  128
#define HID     128
#define OUT_DIM 64
#define CAP     96          // max in-degree (Poisson λ=16 → P(>96) ~ 0)

// Scratch (device globals — no allocations allowed)
__device__ int   g_idx64;                         // 1 if edge_index is int64
__device__ int   g_cur[N_NODES];                  // cursor == in-degree after fill
__device__ float g_dinv[N_NODES];
__device__ float g_hs[(size_t)N_NODES * IN_DIM];  // h[r] * dinv[r]
__device__ float g_agg[(size_t)N_NODES * IN_DIM]; // aggregated features
__device__ int   g_src[(size_t)N_NODES * CAP];    // bucketed source lists (19.2 MB)
__device__ uint2 g_Wg2[IN_DIM * HID];             // Wg as (tf32_hi, tf32_lo)
__device__ uint2 g_Wf2[HID * OUT_DIM];            // Wf as (tf32_hi, tf32_lo)

// ---- tf32 helpers ----
__device__ __forceinline__ uint32_t f2tf(float x) {
    uint32_t r;
    asm("cvt.rna.tf32.f32 %0, %1;" : "=r"(r) : "f"(x));
    return r;
}
__device__ __forceinline__ void mma_tf32(float4& d,
                                         uint32_t a0, uint32_t a1, uint32_t a2, uint32_t a3,
                                         uint32_t b0, uint32_t b1) {
    asm("mma.sync.aligned.m16n8k8.row.col.f32.tf32.tf32.f32 "
        "{%0,%1,%2,%3},{%4,%5,%6,%7},{%8,%9},{%0,%1,%2,%3};"
        : "+f"(d.x), "+f"(d.y), "+f"(d.z), "+f"(d.w)
        : "r"(a0), "r"(a1), "r"(a2), "r"(a3), "r"(b0), "r"(b1));
}

__device__ __forceinline__ int edge_idx(const void* ei, int i) {
    if (g_idx64) return (int)((const long long*)ei)[i];
    return ((const int*)ei)[i];
}

// ---------------------------------------------------------------------------
// k0: zero cursors + split weights into tf32 hi/lo + dtype detection
// ---------------------------------------------------------------------------
__global__ void k_init(const void* __restrict__ ei,
                       const float* __restrict__ Wg,
                       const float* __restrict__ Wf) {
    int i = blockIdx.x * blockDim.x + threadIdx.x;
    if (i < N_NODES) g_cur[i] = 0;
    if (i < IN_DIM * HID) {
        float w = Wg[i];
        uint32_t hi = f2tf(w);
        uint32_t lo = f2tf(w - __uint_as_float(hi));
        g_Wg2[i] = make_uint2(hi, lo);
    }
    if (i < HID * OUT_DIM) {
        float w = Wf[i];
        uint32_t hi = f2tf(w);
        uint32_t lo = f2tf(w - __uint_as_float(hi));
        g_Wf2[i] = make_uint2(hi, lo);
    }
    if (blockIdx.x == 0) {
        __shared__ int s_ok;
        if (threadIdx.x == 0) s_ok = 1;
        __syncthreads();
        long long v = ((const long long*)ei)[threadIdx.x];  // 2KB, in-bounds either way
        if (v < 0 || v >= N_NODES) atomicAnd(&s_ok, 0);
        __syncthreads();
        if (threadIdx.x == 0) g_idx64 = s_ok;
    }
}

// k1: combined count + bucket fill
__global__ void k_fill(const void* __restrict__ ei) {
    int e = blockIdx.x * blockDim.x + threadIdx.x;
    if (e < N_EDGES) {
        int r = edge_idx(ei, e);
        int c = edge_idx(ei, N_EDGES + e);
        int p = atomicAdd(&g_cur[c], 1);
        if (p < CAP) g_src[(size_t)c * CAP + p] = r;
    }
}

// k2: dinv = rsqrt(deg+1), hs = h * dinv
__global__ void k_hs(const float* __restrict__ h) {
    int idx = blockIdx.x * blockDim.x + threadIdx.x;
    if (idx >= N_NODES * 32) return;
    int node = idx >> 5;
    float dn = rsqrtf((float)(g_cur[node] + 1));   // +1 self-loop
    if ((idx & 31) == 0) g_dinv[node] = dn;
    float4 v = ((const float4*)h)[idx];
    v.x *= dn; v.y *= dn; v.z *= dn; v.w *= dn;
    ((float4*)g_hs)[idx] = v;
}

// ---------------------------------------------------------------------------
// k3: gather only (warp per node, low regs, high occupancy):
//     agg[n] = dinv[n]*(hs[n] + sum_in hs[r]); edge loop x4 unrolled.
// ---------------------------------------------------------------------------
__global__ void __launch_bounds__(256) k_gather() {
    int node = (blockIdx.x * blockDim.x + threadIdx.x) >> 5;
    if (node >= N_NODES) return;
    int tx = threadIdx.x & 31;
    const float4* hs4 = (const float4*)g_hs;

    float4 acc = __ldg(hs4 + (size_t)node * 32 + tx);   // self term
    int cnt = __ldg(g_cur + node);
    if (cnt > CAP) cnt = CAP;
    const int* src = g_src + (size_t)node * CAP;
    int p = 0;
    for (; p + 4 <= cnt; p += 4) {
        int r0 = __ldg(src + p + 0);
        int r1 = __ldg(src + p + 1);
        int r2 = __ldg(src + p + 2);
        int r3 = __ldg(src + p + 3);
        float4 v0 = __ldg(hs4 + (size_t)r0 * 32 + tx);
        float4 v1 = __ldg(hs4 + (size_t)r1 * 32 + tx);
        float4 v2 = __ldg(hs4 + (size_t)r2 * 32 + tx);
        float4 v3 = __ldg(hs4 + (size_t)r3 * 32 + tx);
        acc.x += v0.x + v1.x + v2.x + v3.x;
        acc.y += v0.y + v1.y + v2.y + v3.y;
        acc.z += v0.z + v1.z + v2.z + v3.z;
        acc.w += v0.w + v1.w + v2.w + v3.w;
    }
    for (; p < cnt; p++) {
        int r = __ldg(src + p);
        float4 v = __ldg(hs4 + (size_t)r * 32 + tx);
        acc.x += v.x; acc.y += v.y; acc.z += v.z; acc.w += v.w;
    }
    float dn = __ldg(g_dinv + node);
    acc.x *= dn; acc.y *= dn; acc.z *= dn; acc.w *= dn;
    ((float4*)g_agg)[(size_t)node * 32 + tx] = acc;
}

// ---------------------------------------------------------------------------
// k4: tensor-core MLP via mma.sync m16n8k8 tf32, 3xTF32 compensated
//     (a·w ≈ a_hi·w_hi + a_hi·w_lo + a_lo·w_hi; error ~2^-22).
//   Block: 256 thr = 8 warps, 64 nodes. Warp w: nodes 16*(w>>1).., and
//   half (w&1) of the output columns. A-frags from padded smem (stride 132).
// ---------------------------------------------------------------------------
#define SROW 132   // smem row stride in floats (128 + 4 pad: conflict-free frags)

__global__ void __launch_bounds__(256) k_mlp(const float* __restrict__ bg,
                                             const float* __restrict__ bf,
                                             float* __restrict__ out) {
    __shared__ float sA[64 * SROW];   // 33 KB, reused for hidden

    int tid  = threadIdx.x;
    int lane = tid & 31;
    int w    = tid >> 5;
    int gid  = lane >> 2;      // 0..7
    int tig  = lane & 3;       // 0..3
    int s0   = (w >> 1) * 16;  // node slab base (local)
    int half = w & 1;
    int node0 = blockIdx.x * 64;

    // ---- load agg tile into padded smem ----
    for (int i = tid; i < 64 * 32; i += 256) {
        int nl = i >> 5, k4 = i & 31;
        int node = node0 + nl;
        float4 v = make_float4(0.f, 0.f, 0.f, 0.f);
        if (node < N_NODES) v = __ldg((const float4*)g_agg + (size_t)node * 32 + k4);
        *(float4*)&sA[nl * SROW + 4 * k4] = v;
    }
    __syncthreads();

    // ---- phase 1: hid = A @ Wg + bg   (n-range: 64*half .. +63) ----
    int n0 = 64 * half;
    float4 acc[8];
    #pragma unroll
    for (int nt = 0; nt < 8; nt++) {
        float2 b = __ldg((const float2*)(bg + n0 + 8 * nt + 2 * tig));
        acc[nt] = make_float4(b.x, b.y, b.x, b.y);
    }
    #pragma unroll 2
    for (int kt = 0; kt < 16; kt++) {
        int k0 = 8 * kt;
        float f0 = sA[(s0 + gid)     * SROW + k0 + tig];
        float f1 = sA[(s0 + gid + 8) * SROW + k0 + tig];
        float f2 = sA[(s0 + gid)     * SROW + k0 + tig + 4];
        float f3 = sA[(s0 + gid + 8) * SROW + k0 + tig + 4];
        uint32_t ah0 = f2tf(f0), ah1 = f2tf(f1), ah2 = f2tf(f2), ah3 = f2tf(f3);
        uint32_t al0 = f2tf(f0 - __uint_as_float(ah0));
        uint32_t al1 = f2tf(f1 - __uint_as_float(ah1));
        uint32_t al2 = f2tf(f2 - __uint_as_float(ah2));
        uint32_t al3 = f2tf(f3 - __uint_as_float(ah3));
        #pragma unroll
        for (int nt = 0; nt < 8; nt++) {
            int n = n0 + 8 * nt + gid;
            uint2 b0 = __ldg(&g_Wg2[(k0 + tig)     * HID + n]);
            uint2 b1 = __ldg(&g_Wg2[(k0 + tig + 4) * HID + n]);
            mma_tf32(acc[nt], ah0, ah1, ah2, ah3, b0.x, b1.x);   // hi*hi
            mma_tf32(acc[nt], ah0, ah1, ah2, ah3, b0.y, b1.y);   // hi*lo
            mma_tf32(acc[nt], al0, al1, al2, al3, b0.x, b1.x);   // lo*hi
        }
    }
    __syncthreads();   // all A reads done before hidden overwrite

    // relu -> hidden tile (rows = nodes, cols = hid), float2 stores
    #pragma unroll
    for (int nt = 0; nt < 8; nt++) {
        int c = n0 + 8 * nt + 2 * tig;
        float2 lo, hi;
        lo.x = fmaxf(acc[nt].x, 0.f); lo.y = fmaxf(acc[nt].y, 0.f);
        hi.x = fmaxf(acc[nt].z, 0.f); hi.y = fmaxf(acc[nt].w, 0.f);
        *(float2*)&sA[(s0 + gid)     * SROW + c] = lo;
        *(float2*)&sA[(s0 + gid + 8) * SROW + c] = hi;
    }
    __syncthreads();

    // ---- phase 2: out = hid @ Wf + bf   (n-range: 32*half .. +31) ----
    int m0 = 32 * half;
    float4 o[4];
    #pragma unroll
    for (int nt = 0; nt < 4; nt++) {
        float2 b = __ldg((const float2*)(bf + m0 + 8 * nt + 2 * tig));
        o[nt] = make_float4(b.x, b.y, b.x, b.y);
    }
    #pragma unroll 2
    for (int kt = 0; kt < 16; kt++) {
        int k0 = 8 * kt;
        float f0 = sA[(s0 + gid)     * SROW + k0 + tig];
        float f1 = sA[(s0 + gid + 8) * SROW + k0 + tig];
        float f2 = sA[(s0 + gid)     * SROW + k0 + tig + 4];
        float f3 = sA[(s0 + gid + 8) * SROW + k0 + tig + 4];
        uint32_t ah0 = f2tf(f0), ah1 = f2tf(f1), ah2 = f2tf(f2), ah3 = f2tf(f3);
        uint32_t al0 = f2tf(f0 - __uint_as_float(ah0));
        uint32_t al1 = f2tf(f1 - __uint_as_float(ah1));
        uint32_t al2 = f2tf(f2 - __uint_as_float(ah2));
        uint32_t al3 = f2tf(f3 - __uint_as_float(ah3));
        #pragma unroll
        for (int nt = 0; nt < 4; nt++) {
            int n = m0 + 8 * nt + gid;
            uint2 b0 = __ldg(&g_Wf2[(k0 + tig)     * OUT_DIM + n]);
            uint2 b1 = __ldg(&g_Wf2[(k0 + tig + 4) * OUT_DIM + n]);
            mma_tf32(o[nt], ah0, ah1, ah2, ah3, b0.x, b1.x);
            mma_tf32(o[nt], ah0, ah1, ah2, ah3, b0.y, b1.y);
            mma_tf32(o[nt], al0, al1, al2, al3, b0.x, b1.x);
        }
    }

    // store: c0,c1 -> node s0+gid; c2,c3 -> node s0+gid+8
    #pragma unroll
    for (int nt = 0; nt < 4; nt++) {
        int c = m0 + 8 * nt + 2 * tig;
        int na = node0 + s0 + gid;
        int nb = na + 8;
        if (na < N_NODES) {
            float2 v; v.x = o[nt].x; v.y = o[nt].y;
            *(float2*)&out[(size_t)na * OUT_DIM + c] = v;
        }
        if (nb < N_NODES) {
            float2 v; v.x = o[nt].z; v.y = o[nt].w;
            *(float2*)&out[(size_t)nb * OUT_DIM + c] = v;
        }
    }
}

// ---------------------------------------------------------------------------
// launch — inputs: h[f32 N*128], edge_index[2*E int32-or-int64],
//          W_gcn[f32 128*128], b_gcn[f32 128], W_fc[f32 128*64], b_fc[f32 64]
// output: f32 N*64
// ---------------------------------------------------------------------------
extern "C" void kernel_launch(void* const* d_in, const int* in_sizes, int n_in,
                              void* d_out, int out_size) {
    const float* h  = (const float*)d_in[0];
    const void*  ei = d_in[1];
    const float* Wg = (const float*)d_in[2];
    const float* bg = (const float*)d_in[3];
    const float* Wf = (const float*)d_in[4];
    const float* bf = (const float*)d_in[5];
    float* out = (float*)d_out;

    k_init  <<<(N_NODES + 255) / 256, 256>>>(ei, Wg, Wf);
    k_fill  <<<(N_EDGES + 255) / 256, 256>>>(ei);
    k_hs    <<<(N_NODES * 32 + 255) / 256, 256>>>(h);
    k_gather<<<(N_NODES * 32 + 255) / 256, 256>>>();      // warp per node
    k_mlp   <<<(N_NODES + 63) / 64, 256>>>(bg, bf, out);
}

// round 11
// speedup vs baseline: 1.2446x; 1.2446x over previous
#include <cuda_runtime.h>
#include <cuda_bf16.h>
#include <cstdint>

#define N_NODES 50000
#define N_EDGES 800000
#define IN_DIM  128
#define HID     128
#define OUT_DIM 64
#define CAP     96          // max in-degree (Poisson λ=16 → P(>96) ~ 0)

// Scratch (device globals — no allocations allowed)
__device__ int   g_idx64;                         // 1 if edge_index is int64
__device__ int   g_cur[N_NODES];                  // cursor == in-degree after fill
__device__ float g_dinv[N_NODES];
__device__ float g_agg[(size_t)N_NODES * IN_DIM]; // aggregated features
__device__ int   g_src[(size_t)N_NODES * CAP];    // bucketed source lists (19.2 MB)

__device__ __forceinline__ int edge_idx(const void* ei, int i) {
    if (g_idx64) return (int)((const long long*)ei)[i];
    return ((const int*)ei)[i];
}

// ---------------------------------------------------------------------------
// k0: zero cursors + dtype detection (JAX silently downcasts int64 -> int32)
// ---------------------------------------------------------------------------
__global__ void k_init(const void* __restrict__ ei) {
    int i = blockIdx.x * blockDim.x + threadIdx.x;
    if (i < N_NODES) g_cur[i] = 0;
    if (blockIdx.x == 0) {
        __shared__ int s_ok;
        if (threadIdx.x == 0) s_ok = 1;
        __syncthreads();
        long long v = ((const long long*)ei)[threadIdx.x];  // 2KB, in-bounds either way
        if (v < 0 || v >= N_NODES) atomicAnd(&s_ok, 0);
        __syncthreads();
        if (threadIdx.x == 0) g_idx64 = s_ok;
    }
}

// k1: combined count + bucket fill (cursor doubles as in-degree histogram)
__global__ void k_fill(const void* __restrict__ ei) {
    int e = blockIdx.x * blockDim.x + threadIdx.x;
    if (e < N_EDGES) {
        int r = edge_idx(ei, e);
        int c = edge_idx(ei, N_EDGES + e);
        int p = atomicAdd(&g_cur[c], 1);
        if (p < CAP) g_src[(size_t)c * CAP + p] = r;
    }
}

// k2: dinv = rsqrt(deg+1)  (tiny; replaces the full 51MB hs pass)
__global__ void k_dinv() {
    int i = blockIdx.x * blockDim.x + threadIdx.x;
    if (i < N_NODES) g_dinv[i] = rsqrtf((float)(g_cur[i] + 1));
}

// ---------------------------------------------------------------------------
// k3: gather (warp per node, proven 30.8us structure):
//     agg[n] = dinv[n] * (h[n]*dinv[n] + sum_in h[r]*dinv[r])
//     dinv applied inline per edge (broadcast scalar load + FMA; issue headroom)
// ---------------------------------------------------------------------------
__global__ void __launch_bounds__(256) k_gather(const float* __restrict__ h) {
    int node = (blockIdx.x * blockDim.x + threadIdx.x) >> 5;
    if (node >= N_NODES) return;
    int tx = threadIdx.x & 31;
    const float4* h4 = (const float4*)h;

    float dn = __ldg(g_dinv + node);
    float4 acc = __ldg(h4 + (size_t)node * 32 + tx);
    acc.x *= dn; acc.y *= dn; acc.z *= dn; acc.w *= dn;   // self term h[n]*dinv[n]

    int cnt = __ldg(g_cur + node);
    if (cnt > CAP) cnt = CAP;
    const int* src = g_src + (size_t)node * CAP;
    int p = 0;
    for (; p + 4 <= cnt; p += 4) {
        int r0 = __ldg(src + p + 0);
        int r1 = __ldg(src + p + 1);
        int r2 = __ldg(src + p + 2);
        int r3 = __ldg(src + p + 3);
        float d0 = __ldg(g_dinv + r0);
        float d1 = __ldg(g_dinv + r1);
        float d2 = __ldg(g_dinv + r2);
        float d3 = __ldg(g_dinv + r3);
        float4 v0 = __ldg(h4 + (size_t)r0 * 32 + tx);
        float4 v1 = __ldg(h4 + (size_t)r1 * 32 + tx);
        float4 v2 = __ldg(h4 + (size_t)r2 * 32 + tx);
        float4 v3 = __ldg(h4 + (size_t)r3 * 32 + tx);
        acc.x += v0.x * d0 + v1.x * d1 + v2.x * d2 + v3.x * d3;
        acc.y += v0.y * d0 + v1.y * d1 + v2.y * d2 + v3.y * d3;
        acc.z += v0.z * d0 + v1.z * d1 + v2.z * d2 + v3.z * d3;
        acc.w += v0.w * d0 + v1.w * d1 + v2.w * d2 + v3.w * d3;
    }
    for (; p < cnt; p++) {
        int r = __ldg(src + p);
        float d = __ldg(g_dinv + r);
        float4 v = __ldg(h4 + (size_t)r * 32 + tx);
        acc.x += v.x * d; acc.y += v.y * d; acc.z += v.z * d; acc.w += v.w * d;
    }
    acc.x *= dn; acc.y *= dn; acc.z *= dn; acc.w *= dn;
    ((float4*)g_agg)[(size_t)node * 32 + tx] = acc;
}

// ---------------------------------------------------------------------------
// k4: standalone scalar MLP (proven R2 code): out = relu(agg@Wg+bg)@Wf + bf
//   64 nodes/block, 256 threads; 8x4 register tile phase 1, 8x2 phase 2.
//   Natural register allocation (no launch_bounds cap — R9 proved caps spill).
// ---------------------------------------------------------------------------
__global__ void __launch_bounds__(256) k_mlp(const float* __restrict__ Wg,
                                             const float* __restrict__ bg,
                                             const float* __restrict__ Wf,
                                             const float* __restrict__ bf,
                                             float* __restrict__ out) {
    __shared__ float sA[64 * 128];   // 32 KB: input tile, then hidden tile

    int tid = threadIdx.x;
    int tx = tid & 31;
    int ty = tid >> 5;
    int node0 = blockIdx.x * 64;

    // load 64x128 input tile (zero-pad past N)
    for (int i = tid; i < 64 * 32; i += 256) {
        int node = node0 + (i >> 5);
        float4 v = make_float4(0.f, 0.f, 0.f, 0.f);
        if (node < N_NODES) v = __ldg((const float4*)g_agg + (size_t)node * 32 + (i & 31));
        ((float4*)sA)[i] = v;
    }
    __syncthreads();

    // ---- phase 1: hid = A @ Wg + bg ----
    float acc[8][4];
    {
        float4 b = __ldg((const float4*)bg + tx);
        #pragma unroll
        for (int i = 0; i < 8; i++) {
            acc[i][0] = b.x; acc[i][1] = b.y; acc[i][2] = b.z; acc[i][3] = b.w;
        }
    }
    #pragma unroll 4
    for (int k = 0; k < 128; k++) {
        float4 w = __ldg((const float4*)(Wg + k * 128) + tx);
        #pragma unroll
        for (int i = 0; i < 8; i++) {
            float a = sA[(8 * ty + i) * 128 + k];
            acc[i][0] += a * w.x;
            acc[i][1] += a * w.y;
            acc[i][2] += a * w.z;
            acc[i][3] += a * w.w;
        }
    }
    __syncthreads();

    // relu -> hidden tile
    #pragma unroll
    for (int i = 0; i < 8; i++) {
        float4 v;
        v.x = fmaxf(acc[i][0], 0.f);
        v.y = fmaxf(acc[i][1], 0.f);
        v.z = fmaxf(acc[i][2], 0.f);
        v.w = fmaxf(acc[i][3], 0.f);
        ((float4*)sA)[(8 * ty + i) * 32 + tx] = v;
    }
    __syncthreads();

    // ---- phase 2: out = hid @ Wf + bf ----
    float o[8][2];
    {
        float2 b = __ldg((const float2*)bf + tx);
        #pragma unroll
        for (int i = 0; i < 8; i++) { o[i][0] = b.x; o[i][1] = b.y; }
    }
    #pragma unroll 4
    for (int k = 0; k < 128; k++) {
        float2 w = __ldg((const float2*)(Wf + k * 64) + tx);
        #pragma unroll
        for (int i = 0; i < 8; i++) {
            float a = sA[(8 * ty + i) * 128 + k];
            o[i][0] += a * w.x;
            o[i][1] += a * w.y;
        }
    }

    #pragma unroll
    for (int i = 0; i < 8; i++) {
        int node = node0 + 8 * ty + i;
        if (node < N_NODES) {
            float2 v; v.x = o[i][0]; v.y = o[i][1];
            ((float2*)out)[(size_t)node * 32 + tx] = v;
        }
    }
}

// ---------------------------------------------------------------------------
// launch — inputs: h[f32 N*128], edge_index[2*E int32-or-int64],
//          W_gcn[f32 128*128], b_gcn[f32 128], W_fc[f32 128*64], b_fc[f32 64]
// output: f32 N*64
// ---------------------------------------------------------------------------
extern "C" void kernel_launch(void* const* d_in, const int* in_sizes, int n_in,
                              void* d_out, int out_size) {
    const float* h  = (const float*)d_in[0];
    const void*  ei = d_in[1];
    const float* Wg = (const float*)d_in[2];
    const float* bg = (const float*)d_in[3];
    const float* Wf = (const float*)d_in[4];
    const float* bf = (const float*)d_in[5];
    float* out = (float*)d_out;

    k_init  <<<(N_NODES + 255) / 256, 256>>>(ei);
    k_fill  <<<(N_EDGES + 255) / 256, 256>>>(ei);
    k_dinv  <<<(N_NODES + 255) / 256, 256>>>();
    k_gather<<<(N_NODES * 32 + 255) / 256, 256>>>(h);     // warp per node
    k_mlp   <<<(N_NODES + 63) / 64, 256>>>(Wg, bg, Wf, bf, out);
}